// round 8
// baseline (speedup 1.0000x reference)
#include <cuda_runtime.h>
#include <math.h>

#define NB 48
#define CC 512
#define PP 1600
#define KK 64
#define EPSV 1e-12f
#define NSPLIT 3

typedef unsigned long long ull;

// Scratch (device globals; no allocations allowed).
__device__ __align__(16) float g_w[NB * KK * PP];          // soft_assign * hmp
__device__ __align__(16) float g_invn[NB * PP];            // 1/max(||x||,eps)
__device__ __align__(16) float g_hmp[NB * PP];             // heatmap
__device__ __align__(16) float g_t1[NSPLIT * NB * KK * CC]; // partial term1
__device__ __align__(16) float g_wsum3[NSPLIT * NB * KK];  // partial wsum
__device__ __align__(16) float g_knss[NB * KK];            // per-(n,k) sumsq

// packed fp32x2 FMA: d = a*b + d (lane-wise). SASS FFMA2, only via PTX.
#define FFMA2(d, a, b) \
    asm("fma.rn.f32x2 %0, %1, %2, %0;" : "+l"(d) : "l"(a), "l"(b))

__device__ __forceinline__ ull dup_f32x2(float v) {
    ull d;
    asm("mov.b64 %0, {%1, %1};" : "=l"(d) : "f"(v));
    return d;
}
__device__ __forceinline__ float lo32(ull v) { return __uint_as_float((unsigned)v); }
__device__ __forceinline__ float hi32(ull v) { return __uint_as_float((unsigned)(v >> 32)); }

// 64-wide pair layout (a-side / k dim): v = g*8 + 2j + h (g=0..7, j=0..3, h=0..1)
// float slot = j*16 + g*2 + h  (ull slot j*8+g, half h)
__device__ __forceinline__ int pair_idx(int v) {
    return (v & 1) + ((v >> 1) & 3) * 16 + ((v >> 3) << 1);
}
// 128-wide pair layout (b-side): v = g*8 + 2j + h (g=0..15)
// float slot = j*32 + g*2 + h  (ull slot j*16+g, half h)
__device__ __forceinline__ int pair_idx128(int v) {
    return (v & 1) + ((v >> 1) & 3) * 32 + ((v >> 3) << 1);
}

// ---------------------------------------------------------------------------
// K1: per-pixel channel stats: invn and heatmap. One coalesced pass over x.
// ---------------------------------------------------------------------------
__global__ void k_pixstats(const float* __restrict__ x,
                           const float* __restrict__ aw,
                           const float* __restrict__ ab) {
    __shared__ float saw[CC];
    int t = threadIdx.x;
    for (int i = t; i < CC; i += 256) saw[i] = aw[i];
    __syncthreads();

    int pix = blockIdx.x * 256 + t;              // 76800 = 300*256
    int n = pix / PP;
    int p = pix - n * PP;
    const float* xp = x + (size_t)n * CC * PP + p;

    float ss = 0.f, av = 0.f;
#pragma unroll 8
    for (int c = 0; c < CC; c++) {
        float v = xp[(size_t)c * PP];
        ss = fmaf(v, v, ss);
        float r = v > 0.f ? v : 0.f;
        av = fmaf(r, saw[c], av);
    }
    float hm = av + ab[0];
    hm = hm > 0.f ? hm : 0.f;
    float invn = 1.f / fmaxf(sqrtf(ss), EPSV);
    g_invn[pix] = invn;
    g_hmp[pix] = hm;
}

// ---------------------------------------------------------------------------
// K2: logits GEMM (64k x 512c)x(512c x 128p) + softmax over k + w.
// 128 threads (4 warps), micro-tile 8k x 8p, FFMA2, pair-packed smem.
// Grid (13, 48); tile 12 partially masked (13*128 = 1664 > 1600).
// ---------------------------------------------------------------------------
__global__ void __launch_bounds__(128) k_assign(const float* __restrict__ x,
                                                const float* __restrict__ cw) {
    __shared__ ull   ws[32][33];      // [cc][j*8+g]: pairs of conv_w along k
    __shared__ ull   xs[32][65];      // [cc][u*16+g]: pairs of x along p (128 p)
    __shared__ float red[8][128];
    __shared__ float cm[128];
    __shared__ float cs[128];

    int t = threadIdx.x;
    int tx = t & 15;                  // p group: p = tx*8 + (0..7)
    int ty = t >> 4;                  // k group: k = ty*8 + (0..7)
    int n = blockIdx.y;
    int p0 = blockIdx.x * 128;
    const float* xb = x + (size_t)n * CC * PP;

    ull acc[8][4];
#pragma unroll
    for (int i = 0; i < 8; i++)
#pragma unroll
        for (int u = 0; u < 4; u++) acc[i][u] = 0ull;

    for (int c0 = 0; c0 < CC; c0 += 32) {
#pragma unroll
        for (int q = 0; q < 16; q++) {           // conv_w tile: 64k x 32c
            int e = t + q * 128;
            int k = e >> 5, cc = e & 31;
            ((float*)ws[cc])[pair_idx(k)] = cw[k * CC + c0 + cc];
        }
#pragma unroll
        for (int q = 0; q < 16; q++) {           // x tile: 32c x 128p, float2
            int e = t + q * 128;
            int cc = e >> 6, p2 = e & 63;        // p = 2*p2
            int p = p0 + 2 * p2;
            float2 v = (p < PP)
                ? *reinterpret_cast<const float2*>(&xb[(size_t)(c0 + cc) * PP + p])
                : make_float2(0.f, 0.f);
            // p even: g = p2>>2, j = p2&3, ull slot j*16+g
            xs[cc][(p2 & 3) * 16 + (p2 >> 2)] = *reinterpret_cast<ull*>(&v);
        }
        __syncthreads();
#pragma unroll 4
        for (int cc = 0; cc < 32; cc++) {
            ull ap[4], b[4], ad[8];
#pragma unroll
            for (int j = 0; j < 4; j++) ap[j] = ws[cc][j * 8 + ty];
#pragma unroll
            for (int u = 0; u < 4; u++) b[u] = xs[cc][u * 16 + tx];
#pragma unroll
            for (int j = 0; j < 4; j++) {
                ad[2 * j]     = dup_f32x2(lo32(ap[j]));
                ad[2 * j + 1] = dup_f32x2(hi32(ap[j]));
            }
#pragma unroll
            for (int i = 0; i < 8; i++)
#pragma unroll
                for (int u = 0; u < 4; u++) FFMA2(acc[i][u], ad[i], b[u]);
        }
        __syncthreads();
    }

    // unpack + scale by invn[p]   (p = p0 + tx*8 + 2u + h)
    int pb = p0 + tx * 8;
    float f[8][8], hm[8];
#pragma unroll
    for (int u = 0; u < 4; u++) {
        int p = pb + 2 * u;
        float2 iv = (p < PP) ? *reinterpret_cast<const float2*>(&g_invn[n * PP + p])
                             : make_float2(0.f, 0.f);
        float2 hv = (p < PP) ? *reinterpret_cast<const float2*>(&g_hmp[n * PP + p])
                             : make_float2(0.f, 0.f);
        hm[2 * u] = hv.x; hm[2 * u + 1] = hv.y;
#pragma unroll
        for (int i = 0; i < 8; i++) {
            f[i][2 * u]     = lo32(acc[i][u]) * iv.x;
            f[i][2 * u + 1] = hi32(acc[i][u]) * iv.y;
        }
    }

    // softmax over k = 64 (8 local x 8 ty groups)
#pragma unroll
    for (int j = 0; j < 8; j++) {
        float m = f[0][j];
#pragma unroll
        for (int i = 1; i < 8; i++) m = fmaxf(m, f[i][j]);
        red[ty][tx * 8 + j] = m;
    }
    __syncthreads();
    {
        float m = red[0][t];
#pragma unroll
        for (int r = 1; r < 8; r++) m = fmaxf(m, red[r][t]);
        cm[t] = m;
    }
    __syncthreads();
#pragma unroll
    for (int j = 0; j < 8; j++) {
        float m = cm[tx * 8 + j];
        float s = 0.f;
#pragma unroll
        for (int i = 0; i < 8; i++) {
            f[i][j] = __expf(f[i][j] - m);
            s += f[i][j];
        }
        red[ty][tx * 8 + j] = s;
    }
    __syncthreads();
    {
        float s = red[0][t];
#pragma unroll
        for (int r = 1; r < 8; r++) s += red[r][t];
        cs[t] = s;
    }
    __syncthreads();

    float* wb = g_w + (size_t)n * KK * PP;
    float sc[8];
#pragma unroll
    for (int j = 0; j < 8; j++) sc[j] = hm[j] / cs[tx * 8 + j];
#pragma unroll
    for (int i = 0; i < 8; i++) {
        float* row = wb + (size_t)(ty * 8 + i) * PP + pb;
#pragma unroll
        for (int u = 0; u < 4; u++) {
            if (pb + 2 * u < PP) {
                float2 v;
                v.x = f[i][2 * u]     * sc[2 * u];
                v.y = f[i][2 * u + 1] * sc[2 * u + 1];
                reinterpret_cast<float2*>(row)[u] = v;
            }
        }
    }
}

// ---------------------------------------------------------------------------
// K3: term1 partial GEMM: (64k x ~533p)x(~533p x 128c) -> g_t1[split];
// invn folded into x side; wsum per split by cb==0 blocks.
// 128 threads, 8k x 8c micro-tile. Grid (4 cb, 48 n, 3 split) = 576 blocks.
// ---------------------------------------------------------------------------
__global__ void __launch_bounds__(128) k_vladgemm(const float* __restrict__ x) {
    __shared__ ull   wsp[32][33];     // [pp][j*8+g]: pairs of w along k
    __shared__ ull   xsc[32][65];     // [pp][u*16+g]: pairs of x*invn along c
    __shared__ float invs[544];

    int t = threadIdx.x;
    int tx = t & 15;                  // c group
    int ty = t >> 4;                  // k group
    int cb = blockIdx.x, n = blockIdx.y, sp = blockIdx.z;
    int c0 = cb * 128;
    int ps0 = sp * 544;
    int plen = (sp == 2) ? 512 : 544;
    const float* xb = x + (size_t)n * CC * PP;
    const float* wb = g_w + (size_t)n * KK * PP;

    for (int i = t; i < plen; i += 128) invs[i] = g_invn[n * PP + ps0 + i];

    ull acc[8][4];
#pragma unroll
    for (int i = 0; i < 8; i++)
#pragma unroll
        for (int u = 0; u < 4; u++) acc[i][u] = 0ull;
    float wl = 0.f;
    int idx_k = pair_idx(t & 63);     // wsum readback (threads t<64 only)
    __syncthreads();

    for (int pl = 0; pl < plen; pl += 32) {
        int p0 = ps0 + pl;
#pragma unroll
        for (int q = 0; q < 8; q++) {            // w tile: 64k x 32p, float2
            int e = t + q * 128;
            int k = e >> 4, p2 = e & 15;         // p = p0 + 2*p2
            float2 v = *reinterpret_cast<const float2*>(&wb[(size_t)k * PP + p0 + 2 * p2]);
            int col = pair_idx(k);
            ((float*)wsp[2 * p2])[col]     = v.x;
            ((float*)wsp[2 * p2 + 1])[col] = v.y;
        }
#pragma unroll
        for (int q = 0; q < 16; q++) {           // x tile: 128c x 32p, float2, scaled
            int e = t + q * 128;
            int cl = e >> 4, p2 = e & 15;
            float2 v = *reinterpret_cast<const float2*>(&xb[(size_t)(c0 + cl) * PP + p0 + 2 * p2]);
            int col = pair_idx128(cl);
            ((float*)xsc[2 * p2])[col]     = v.x * invs[pl + 2 * p2];
            ((float*)xsc[2 * p2 + 1])[col] = v.y * invs[pl + 2 * p2 + 1];
        }
        __syncthreads();
        if (cb == 0 && t < 64) {
#pragma unroll 8
            for (int pp = 0; pp < 32; pp++) wl += ((float*)wsp[pp])[idx_k];
        }
#pragma unroll 4
        for (int pp = 0; pp < 32; pp++) {
            ull ap[4], b[4], ad[8];
#pragma unroll
            for (int j = 0; j < 4; j++) ap[j] = wsp[pp][j * 8 + ty];
#pragma unroll
            for (int u = 0; u < 4; u++) b[u] = xsc[pp][u * 16 + tx];
#pragma unroll
            for (int j = 0; j < 4; j++) {
                ad[2 * j]     = dup_f32x2(lo32(ap[j]));
                ad[2 * j + 1] = dup_f32x2(hi32(ap[j]));
            }
#pragma unroll
            for (int i = 0; i < 8; i++)
#pragma unroll
                for (int u = 0; u < 4; u++) FFMA2(acc[i][u], ad[i], b[u]);
        }
        __syncthreads();
    }

    float* ob = g_t1 + ((size_t)sp * NB + n) * KK * CC;
#pragma unroll
    for (int i = 0; i < 8; i++) {
        float* row = ob + (size_t)(ty * 8 + i) * CC + c0 + tx * 8;
#pragma unroll
        for (int u = 0; u < 4; u++) {
            float2 v;
            v.x = lo32(acc[i][u]);
            v.y = hi32(acc[i][u]);
            reinterpret_cast<float2*>(row)[u] = v;
        }
    }
    if (cb == 0 && t < 64) g_wsum3[(sp * NB + n) * KK + t] = wl;
}

// ---------------------------------------------------------------------------
// K4: vlad = sum(term1 partials) - wsum*centroid, intra-L2-norm per (n,k).
// ---------------------------------------------------------------------------
__global__ void k_intranorm(float* __restrict__ out,
                            const float* __restrict__ cent) {
    int nk = blockIdx.x;
    int k = nk & 63;
    int t = threadIdx.x;
    float wsv = g_wsum3[nk] + g_wsum3[NB * KK + nk] + g_wsum3[2 * NB * KK + nk];
    size_t base = (size_t)nk * CC;
    const float* cb = cent + (size_t)k * CC;

    float v[4];
    float ss = 0.f;
#pragma unroll
    for (int q = 0; q < 4; q++) {
        int c = t + 128 * q;
        float tv = g_t1[base + c] + g_t1[(size_t)NB * KK * CC + base + c]
                 + g_t1[2 * (size_t)NB * KK * CC + base + c];
        v[q] = tv - wsv * cb[c];
        ss = fmaf(v[q], v[q], ss);
    }
#pragma unroll
    for (int o = 16; o > 0; o >>= 1) ss += __shfl_xor_sync(0xffffffffu, ss, o);
    __shared__ float sred[4];
    if ((t & 31) == 0) sred[t >> 5] = ss;
    __syncthreads();
    float tot = sred[0] + sred[1] + sred[2] + sred[3];
    float invv = 1.f / fmaxf(sqrtf(tot), EPSV);
#pragma unroll
    for (int q = 0; q < 4; q++) out[base + t + 128 * q] = v[q] * invv;
    if (t == 0) g_knss[nk] = tot * invv * invv;
}

// ---------------------------------------------------------------------------
// K5: global L2 norm per n. Grid (48, 16), 2048 elems per block.
// ---------------------------------------------------------------------------
__global__ void k_globalnorm(float* __restrict__ out) {
    int n = blockIdx.x, t = threadIdx.x;
    float gs = 0.f;
#pragma unroll
    for (int i = 0; i < KK; i++) gs += g_knss[n * KK + i];
    float sc = 1.f / fmaxf(sqrtf(gs), EPSV);
    size_t base = (size_t)n * KK * CC + (size_t)blockIdx.y * 2048;
#pragma unroll
    for (int q = 0; q < 8; q++) out[base + t + 256 * q] *= sc;
}

// ---------------------------------------------------------------------------
extern "C" void kernel_launch(void* const* d_in, const int* in_sizes, int n_in,
                              void* d_out, int out_size) {
    const float* x  = (const float*)d_in[0];   // [48,512,40,40]
    const float* cw = (const float*)d_in[1];   // [64,512]
    const float* aw = (const float*)d_in[2];   // [1,512]
    const float* ab = (const float*)d_in[3];   // [1]
    const float* ct = (const float*)d_in[4];   // [64,512]
    float* out = (float*)d_out;                // [48, 32768]

    k_pixstats<<<300, 256>>>(x, aw, ab);
    k_assign<<<dim3(13, 48), 128>>>(x, cw);
    k_vladgemm<<<dim3(4, 48, NSPLIT), 128>>>(x);
    k_intranorm<<<NB * KK, 128>>>(out, ct);
    k_globalnorm<<<dim3(48, 16), 256>>>(out);
}

// round 10
// speedup vs baseline: 1.4600x; 1.4600x over previous
#include <cuda_runtime.h>
#include <math.h>

#define NB 48
#define CC 512
#define PP 1600
#define KK 64
#define EPSV 1e-12f

typedef unsigned long long ull;

// Scratch (device globals; no allocations allowed).
__device__ __align__(16) float g_w[NB * KK * PP];      // soft_assign * hmp   [n][k][p]
__device__ __align__(16) float g_invn[NB * PP];        // 1/max(||x||, eps) per pixel
__device__ __align__(16) float g_wsum[NB * KK];        // sum_p w
__device__ __align__(16) float g_knss[NB * KK];        // per-(n,k) sumsq of intra-normed vec

// packed fp32x2 FMA: d = a*b + d (lane-wise). SASS FFMA2, only via PTX.
#define FFMA2(d, a, b) \
    asm("fma.rn.f32x2 %0, %1, %2, %0;" : "+l"(d) : "l"(a), "l"(b))

__device__ __forceinline__ ull dup_f32x2(float v) {
    ull d;
    asm("mov.b64 %0, {%1, %1};" : "=l"(d) : "f"(v));
    return d;
}
__device__ __forceinline__ float lo32(ull v) { return __uint_as_float((unsigned)v); }
__device__ __forceinline__ float hi32(ull v) { return __uint_as_float((unsigned)(v >> 32)); }

// pair-interleaved float index within a 64-wide tile dimension:
// value v (0..63): v = g*8 + 2*j + h  (g = v>>3, j = (v>>1)&3, h = v&1)
// float offset = j*16 + g*2 + h  == ull slot (j*8 + g), half h.
__device__ __forceinline__ int pair_idx(int v) {
    return (v & 1) + ((v >> 1) & 3) * 16 + ((v >> 3) << 1);
}

// ---------------------------------------------------------------------------
// K2: fused pixstats + logits GEMM (64k x 512c)x(512c x 64p) + softmax + w.
// 64 threads, micro-tile 8k x 8p, f32x2 FMA, pair-packed smem. Grid (25,48).
// Thread t owns pixel p0+t for the stats accumulation (x tile fill maps
// thread t -> pixel p0+t, channel chunk q).
// ---------------------------------------------------------------------------
__global__ void __launch_bounds__(64) k_assign(const float* __restrict__ x,
                                               const float* __restrict__ cw,
                                               const float* __restrict__ aw,
                                               const float* __restrict__ ab) {
    __shared__ ull   ws[32][33];      // [cc][j*8+g] = pairs of conv_w along k
    __shared__ ull   xs[32][33];      // [cc][u*8+g] = pairs of x along p
    __shared__ float saw[CC];
    __shared__ float red[8][64];
    __shared__ float cm[64];
    __shared__ float cs[64];
    __shared__ float sinv[64];
    __shared__ float shm[64];

    int t = threadIdx.x;
    int tx = t & 7;                   // p group: p = tx*8 + (0..7)
    int ty = t >> 3;                  // k group: k = ty*8 + (0..7)
    int n = blockIdx.y;
    int p0 = blockIdx.x * 64;
    const float* xb = x + (size_t)n * CC * PP;
    float bias = ab[0];

    for (int i = t; i < CC; i += 64) saw[i] = aw[i];

    ull acc[8][4];
#pragma unroll
    for (int i = 0; i < 8; i++)
#pragma unroll
        for (int u = 0; u < 4; u++) acc[i][u] = 0ull;

    float ss = 0.f, av = 0.f;         // pixel p0+t channel stats
    int idx_t = pair_idx(t);
    __syncthreads();

    for (int c0 = 0; c0 < CC; c0 += 32) {
#pragma unroll
        for (int q = 0; q < 32; q++) {           // conv_w tile: 64k x 32c
            int e = t + q * 64;
            int k = e >> 5, cc = e & 31;
            ((float*)ws[cc])[pair_idx(k)] = cw[k * CC + c0 + cc];
        }
#pragma unroll
        for (int q = 0; q < 32; q++) {           // x tile: 32c x 64p (thread t -> pixel t)
            float v = xb[(size_t)(c0 + q) * PP + p0 + t];
            ss = fmaf(v, v, ss);
            float r = v > 0.f ? v : 0.f;
            av = fmaf(r, saw[c0 + q], av);
            ((float*)xs[q])[idx_t] = v;
        }
        __syncthreads();
#pragma unroll 4
        for (int cc = 0; cc < 32; cc++) {
            ull ap[4], b[4], ad[8];
#pragma unroll
            for (int j = 0; j < 4; j++) ap[j] = ws[cc][j * 8 + ty];
#pragma unroll
            for (int u = 0; u < 4; u++) b[u] = xs[cc][u * 8 + tx];
#pragma unroll
            for (int j = 0; j < 4; j++) {
                ad[2 * j]     = dup_f32x2(lo32(ap[j]));
                ad[2 * j + 1] = dup_f32x2(hi32(ap[j]));
            }
#pragma unroll
            for (int i = 0; i < 8; i++)
#pragma unroll
                for (int u = 0; u < 4; u++) FFMA2(acc[i][u], ad[i], b[u]);
        }
        __syncthreads();
    }

    // finalize stats for pixel p0+t, publish to smem + g_invn
    {
        float invn = 1.f / fmaxf(sqrtf(ss), EPSV);
        float hmv = av + bias;
        hmv = hmv > 0.f ? hmv : 0.f;
        g_invn[n * PP + p0 + t] = invn;
        sinv[t] = invn;
        shm[t] = hmv;
    }
    __syncthreads();

    // unpack + scale by invn[p]   (p = tx*8 + j)
    float f[8][8], hm[8];
#pragma unroll
    for (int u = 0; u < 4; u++) {
        float ivx = sinv[tx * 8 + 2 * u], ivy = sinv[tx * 8 + 2 * u + 1];
        hm[2 * u] = shm[tx * 8 + 2 * u];
        hm[2 * u + 1] = shm[tx * 8 + 2 * u + 1];
#pragma unroll
        for (int i = 0; i < 8; i++) {
            f[i][2 * u]     = lo32(acc[i][u]) * ivx;
            f[i][2 * u + 1] = hi32(acc[i][u]) * ivy;
        }
    }

    // softmax over k = 64 (8 local x 8 ty groups)
#pragma unroll
    for (int j = 0; j < 8; j++) {
        float m = f[0][j];
#pragma unroll
        for (int i = 1; i < 8; i++) m = fmaxf(m, f[i][j]);
        red[ty][tx * 8 + j] = m;
    }
    __syncthreads();
    {
        float m = red[0][t];
#pragma unroll
        for (int r = 1; r < 8; r++) m = fmaxf(m, red[r][t]);
        cm[t] = m;
    }
    __syncthreads();
#pragma unroll
    for (int j = 0; j < 8; j++) {
        float m = cm[tx * 8 + j];
        float s = 0.f;
#pragma unroll
        for (int i = 0; i < 8; i++) {
            f[i][j] = __expf(f[i][j] - m);
            s += f[i][j];
        }
        red[ty][tx * 8 + j] = s;
    }
    __syncthreads();
    {
        float s = red[0][t];
#pragma unroll
        for (int r = 1; r < 8; r++) s += red[r][t];
        cs[t] = s;
    }
    __syncthreads();

    float* wb = g_w + (size_t)n * KK * PP;
    float sc[8];
#pragma unroll
    for (int j = 0; j < 8; j++) sc[j] = hm[j] / cs[tx * 8 + j];
#pragma unroll
    for (int i = 0; i < 8; i++) {
        float* row = wb + (size_t)(ty * 8 + i) * PP + p0 + tx * 8;
#pragma unroll
        for (int u = 0; u < 4; u++) {
            float2 v;
            v.x = f[i][2 * u]     * sc[2 * u];
            v.y = f[i][2 * u + 1] * sc[2 * u + 1];
            reinterpret_cast<float2*>(row)[u] = v;
        }
    }
}

// ---------------------------------------------------------------------------
// K3: term1 GEMM: (64k x 1600p)x(1600p x 64c) -> term1[k,c]; invn folded into
// x side; wsum computed by cb==0 blocks. 64 threads, 8k x 8c tile. Grid (8,48).
// ---------------------------------------------------------------------------
__global__ void __launch_bounds__(64) k_vladgemm(const float* __restrict__ x,
                                                 float* __restrict__ out) {
    __shared__ ull   wsp[32][33];     // [pp][j*8+g] = pairs of w along k
    __shared__ ull   xsc[32][33];     // [pp][u*8+g] = pairs of x*invn along c
    __shared__ float invs[PP];

    int t = threadIdx.x;
    int tx = t & 7;                   // c group
    int ty = t >> 3;                  // k group
    int cb = blockIdx.x, n = blockIdx.y;
    int c0 = cb * 64;
    const float* xb = x + (size_t)n * CC * PP;
    const float* wb = g_w + (size_t)n * KK * PP;

    for (int i = t; i < PP; i += 64) invs[i] = g_invn[n * PP + i];

    ull acc[8][4];
#pragma unroll
    for (int i = 0; i < 8; i++)
#pragma unroll
        for (int u = 0; u < 4; u++) acc[i][u] = 0ull;
    float wl = 0.f;
    int idx_t = pair_idx(t);          // for wsum readback (t = k)
    __syncthreads();

    for (int p0 = 0; p0 < PP; p0 += 32) {
#pragma unroll
        for (int q = 0; q < 32; q++) {           // w tile: 64k x 32p
            int e = t + q * 64;
            int k = e >> 5, pp = e & 31;
            ((float*)wsp[pp])[pair_idx(k)] = wb[(size_t)k * PP + p0 + pp];
        }
#pragma unroll
        for (int q = 0; q < 32; q++) {           // x tile: 64c x 32p, scaled
            int e = t + q * 64;
            int cl = e >> 5, pp = e & 31;
            ((float*)xsc[pp])[pair_idx(cl)] =
                xb[(size_t)(c0 + cl) * PP + p0 + pp] * invs[p0 + pp];
        }
        __syncthreads();
        if (cb == 0) {
#pragma unroll 8
            for (int pp = 0; pp < 32; pp++) wl += ((float*)wsp[pp])[idx_t];
        }
#pragma unroll 4
        for (int pp = 0; pp < 32; pp++) {
            ull ap[4], b[4], ad[8];
#pragma unroll
            for (int j = 0; j < 4; j++) ap[j] = wsp[pp][j * 8 + ty];
#pragma unroll
            for (int u = 0; u < 4; u++) b[u] = xsc[pp][u * 8 + tx];
#pragma unroll
            for (int j = 0; j < 4; j++) {
                ad[2 * j]     = dup_f32x2(lo32(ap[j]));
                ad[2 * j + 1] = dup_f32x2(hi32(ap[j]));
            }
#pragma unroll
            for (int i = 0; i < 8; i++)
#pragma unroll
                for (int u = 0; u < 4; u++) FFMA2(acc[i][u], ad[i], b[u]);
        }
        __syncthreads();
    }

    float* ob = out + (size_t)n * KK * CC;
#pragma unroll
    for (int i = 0; i < 8; i++) {
        float* row = ob + (size_t)(ty * 8 + i) * CC + c0 + tx * 8;
#pragma unroll
        for (int u = 0; u < 4; u++) {
            float2 v;
            v.x = lo32(acc[i][u]);
            v.y = hi32(acc[i][u]);
            reinterpret_cast<float2*>(row)[u] = v;
        }
    }
    if (cb == 0) g_wsum[n * KK + t] = wl;
}

// ---------------------------------------------------------------------------
// K4: vlad = term1 - wsum*centroid, intra-L2-norm per (n,k). 3072 blocks x 128.
// ---------------------------------------------------------------------------
__global__ void k_intranorm(float* __restrict__ out,
                            const float* __restrict__ cent) {
    int nk = blockIdx.x;
    int k = nk & 63;
    int t = threadIdx.x;
    float wsv = g_wsum[nk];
    size_t base = (size_t)nk * CC;
    const float* cb = cent + (size_t)k * CC;

    float v[4];
    float ss = 0.f;
#pragma unroll
    for (int q = 0; q < 4; q++) {
        int c = t + 128 * q;
        v[q] = out[base + c] - wsv * cb[c];
        ss = fmaf(v[q], v[q], ss);
    }
#pragma unroll
    for (int o = 16; o > 0; o >>= 1) ss += __shfl_xor_sync(0xffffffffu, ss, o);
    __shared__ float sred[4];
    if ((t & 31) == 0) sred[t >> 5] = ss;
    __syncthreads();
    float tot = sred[0] + sred[1] + sred[2] + sred[3];
    float invv = 1.f / fmaxf(sqrtf(tot), EPSV);
#pragma unroll
    for (int q = 0; q < 4; q++) out[base + t + 128 * q] = v[q] * invv;
    if (t == 0) g_knss[nk] = tot * invv * invv;
}

// ---------------------------------------------------------------------------
// K5: global L2 norm per n. Grid (48, 16), 2048 elems per block.
// ---------------------------------------------------------------------------
__global__ void k_globalnorm(float* __restrict__ out) {
    int n = blockIdx.x, t = threadIdx.x;
    float gs = 0.f;
#pragma unroll
    for (int i = 0; i < KK; i++) gs += g_knss[n * KK + i];
    float sc = 1.f / fmaxf(sqrtf(gs), EPSV);
    size_t base = (size_t)n * KK * CC + (size_t)blockIdx.y * 2048;
#pragma unroll
    for (int q = 0; q < 8; q++) out[base + t + 256 * q] *= sc;
}

// ---------------------------------------------------------------------------
extern "C" void kernel_launch(void* const* d_in, const int* in_sizes, int n_in,
                              void* d_out, int out_size) {
    const float* x  = (const float*)d_in[0];   // [48,512,40,40]
    const float* cw = (const float*)d_in[1];   // [64,512]
    const float* aw = (const float*)d_in[2];   // [1,512]
    const float* ab = (const float*)d_in[3];   // [1]
    const float* ct = (const float*)d_in[4];   // [64,512]
    float* out = (float*)d_out;                // [48, 32768]

    k_assign<<<dim3(25, 48), 64>>>(x, cw, aw, ab);
    k_vladgemm<<<dim3(8, 48), 64>>>(x, out);
    k_intranorm<<<NB * KK, 128>>>(out, ct);
    k_globalnorm<<<dim3(48, 16), 256>>>(out);
}

// round 13
// speedup vs baseline: 1.5569x; 1.0664x over previous
#include <cuda_runtime.h>
#include <cuda_bf16.h>
#include <math.h>

#define NB 48
#define CC 512
#define PP 1600
#define KK 64
#define EPSV 1e-12f
#define NPB 13
#define RSTR 144   // smem tile row stride in bytes (72 bf16: 64 data + 8 pad)

typedef unsigned long long ull;
typedef unsigned int u32;

// Scratch (device globals; no allocations allowed).
__device__ __align__(16) u32   g_wpk[NB * KK * PP];     // w packed bf16 hi|lo
__device__ __align__(16) float g_invn[NB * PP];         // 1/max(||x||,eps)
__device__ __align__(16) float g_wsump[NB * NPB * KK];  // per-pblock wsum partials
__device__ __align__(16) float g_knss[NB * KK];         // per-(n,k) sumsq

// ---------------- low-level helpers ----------------
__device__ __forceinline__ u32 smem_u32(const void* p) {
    return (u32)__cvta_generic_to_shared(p);
}
__device__ __forceinline__ void sts32(u32 a, u32 v) {
    asm volatile("st.shared.b32 [%0], %1;" :: "r"(a), "r"(v));
}
__device__ __forceinline__ void sts128(u32 a, u32 x, u32 y, u32 z, u32 w) {
    asm volatile("st.shared.v4.b32 [%0], {%1,%2,%3,%4};" :: "r"(a), "r"(x), "r"(y), "r"(z), "r"(w));
}
__device__ __forceinline__ void stsf(u32 a, float v) {
    asm volatile("st.shared.f32 [%0], %1;" :: "r"(a), "f"(v));
}
__device__ __forceinline__ float ldsf(u32 a) {
    float v; asm volatile("ld.shared.f32 %0, [%1];" : "=f"(v) : "r"(a)); return v;
}

// split 2 floats into packed bf16 hi-plane and lo-plane (residual) words.
// hp = {bf16(v1) , bf16(v0)}   (v0 in low half)
__device__ __forceinline__ u32 bsplit2(float v0, float v1, u32& lp) {
    u32 hp;
    asm("cvt.rn.bf16x2.f32 %0, %1, %2;" : "=r"(hp) : "f"(v1), "f"(v0));
    float r0 = v0 - __uint_as_float(hp << 16);
    float r1 = v1 - __uint_as_float(hp & 0xffff0000u);
    asm("cvt.rn.bf16x2.f32 %0, %1, %2;" : "=r"(lp) : "f"(r1), "f"(r0));
    return hp;
}

__device__ __forceinline__ void ldm4(u32 a, u32* r) {
    asm volatile("ldmatrix.sync.aligned.m8n8.x4.shared.b16 {%0,%1,%2,%3}, [%4];"
        : "=r"(r[0]), "=r"(r[1]), "=r"(r[2]), "=r"(r[3]) : "r"(a));
}
__device__ __forceinline__ void mma_bf16(float* d, const u32* a, u32 b0, u32 b1) {
    asm volatile("mma.sync.aligned.m16n8k16.row.col.f32.bf16.bf16.f32 "
        "{%0,%1,%2,%3}, {%4,%5,%6,%7}, {%8,%9}, {%0,%1,%2,%3};"
        : "+f"(d[0]), "+f"(d[1]), "+f"(d[2]), "+f"(d[3])
        : "r"(a[0]), "r"(a[1]), "r"(a[2]), "r"(a[3]), "r"(b0), "r"(b1));
}

// smem tile offsets (bytes, from dynamic smem base)
#define AHI 0
#define ALO 18432
#define BHI 36864
#define BLO 46080
#define XTRA 55296          // saw (K2, 2048B) or invs (K3, 6400B)
#define SMEM_K2 57344
#define SMEM_K3 61696

// ---------------------------------------------------------------------------
// K2: fused pixstats + logits MMA D[p,k] + softmax + w writeout.
// Block: n, 128-p tile. 128 thr / 4 warps, warp tile 32p x 64k, K=512 in 8
// stages of 64c. 3-term bf16 hi/lo split HMMA. Grid (13, 48).
// ---------------------------------------------------------------------------
__global__ void __launch_bounds__(128)
k_assign(const float* __restrict__ x, const float* __restrict__ cw,
         const float* __restrict__ aw, const float* __restrict__ ab) {
    extern __shared__ unsigned char dsm[];
    __shared__ float sinv[128], shm[128];

    int t = threadIdx.x, wid = t >> 5, lane = t & 31;
    int n = blockIdx.y, pb = blockIdx.x;
    int p0 = pb * 128;
    const float* xb = x + (size_t)n * CC * PP;
    u32 base = smem_u32(dsm);
    u32 sawo = base + XTRA;

    for (int i = t; i < CC; i += 128) stsf(sawo + 4 * i, aw[i]);

    int p = p0 + t;
    bool pv = p < PP;
    float ss = 0.f, av = 0.f;
    float bias = ab[0];

    // ldmatrix lane offsets
    int gr8 = lane & 7, sel = lane >> 3;
    int lrow = gr8 + (sel & 1) * 8;
    int lcolb = ((sel >> 1) * 8) * 2;                 // col offset in bytes
    u32 aoff = (u32)((wid * 32 + lrow) * RSTR + lcolb);
    u32 boff = (u32)(lrow * RSTR + lcolb);

    float acc[2][8][4];
#pragma unroll
    for (int mt = 0; mt < 2; mt++)
#pragma unroll
        for (int nt = 0; nt < 8; nt++)
#pragma unroll
            for (int r = 0; r < 4; r++) acc[mt][nt][r] = 0.f;
    __syncthreads();

    for (int st = 0; st < 8; st++) {
        int c0 = st * 64;
        // A fill: thread t = pixel row t; 64 c values, stats fused
#pragma unroll
        for (int cb8 = 0; cb8 < 8; cb8++) {
            float v[8];
#pragma unroll
            for (int i = 0; i < 8; i++)
                v[i] = pv ? xb[(size_t)(c0 + cb8 * 8 + i) * PP + p] : 0.f;
            u32 hp[4], lp[4];
#pragma unroll
            for (int i = 0; i < 4; i++) {
                hp[i] = bsplit2(v[2 * i], v[2 * i + 1], lp[i]);
                ss = fmaf(v[2 * i], v[2 * i], ss);
                ss = fmaf(v[2 * i + 1], v[2 * i + 1], ss);
                av = fmaf(fmaxf(v[2 * i], 0.f),     ldsf(sawo + 4 * (c0 + cb8 * 8 + 2 * i)),     av);
                av = fmaf(fmaxf(v[2 * i + 1], 0.f), ldsf(sawo + 4 * (c0 + cb8 * 8 + 2 * i + 1)), av);
            }
            u32 off = (u32)(t * RSTR + cb8 * 16);
            sts128(base + AHI + off, hp[0], hp[1], hp[2], hp[3]);
            sts128(base + ALO + off, lp[0], lp[1], lp[2], lp[3]);
        }
        // B fill: cw [64k x 64c]
#pragma unroll
        for (int q = 0; q < 16; q++) {
            int e = t + q * 128;
            int k = e >> 5, c2 = e & 31;
            float2 wv = *reinterpret_cast<const float2*>(&cw[k * CC + c0 + 2 * c2]);
            u32 lp, hp = bsplit2(wv.x, wv.y, lp);
            u32 off = (u32)(k * RSTR + c2 * 4);
            sts32(base + BHI + off, hp);
            sts32(base + BLO + off, lp);
        }
        __syncthreads();
#pragma unroll
        for (int kc = 0; kc < 4; kc++) {
            u32 ah[2][4], al[2][4];
            ldm4(base + AHI + aoff + kc * 32, ah[0]);
            ldm4(base + AHI + aoff + 16 * RSTR + kc * 32, ah[1]);
            ldm4(base + ALO + aoff + kc * 32, al[0]);
            ldm4(base + ALO + aoff + 16 * RSTR + kc * 32, al[1]);
#pragma unroll
            for (int j = 0; j < 4; j++) {
                u32 bh[4], bl[4];
                ldm4(base + BHI + boff + j * 16 * RSTR + kc * 32, bh);
                ldm4(base + BLO + boff + j * 16 * RSTR + kc * 32, bl);
#pragma unroll
                for (int mt = 0; mt < 2; mt++) {
                    mma_bf16(acc[mt][2 * j],     ah[mt], bh[0], bh[2]);
                    mma_bf16(acc[mt][2 * j],     ah[mt], bl[0], bl[2]);
                    mma_bf16(acc[mt][2 * j],     al[mt], bh[0], bh[2]);
                    mma_bf16(acc[mt][2 * j + 1], ah[mt], bh[1], bh[3]);
                    mma_bf16(acc[mt][2 * j + 1], ah[mt], bl[1], bl[3]);
                    mma_bf16(acc[mt][2 * j + 1], al[mt], bh[1], bh[3]);
                }
            }
        }
        __syncthreads();
    }

    // stats finalize (pixel p0+t)
    {
        float invn = 1.f / fmaxf(sqrtf(ss), EPSV);
        float hmv = fmaxf(av + bias, 0.f);
        if (pv) g_invn[n * PP + p] = invn;
        sinv[t] = invn;
        shm[t] = hmv;
    }
    __syncthreads();

    // softmax on fragments + stage w[p][k] in smem (overlays dead tiles)
    int gr = lane >> 2, q = lane & 3;
    u32 wst = base;                       // [128][65] f32
#pragma unroll
    for (int mt = 0; mt < 2; mt++) {
        int r0 = wid * 32 + mt * 16 + gr;
        int r1 = r0 + 8;
        float iv0 = sinv[r0], iv1 = sinv[r1];
        float f0[16], f1[16];
        float m0 = -1e30f, m1 = -1e30f;
#pragma unroll
        for (int nt = 0; nt < 8; nt++) {
            f0[2 * nt]     = acc[mt][nt][0] * iv0;
            f0[2 * nt + 1] = acc[mt][nt][1] * iv0;
            f1[2 * nt]     = acc[mt][nt][2] * iv1;
            f1[2 * nt + 1] = acc[mt][nt][3] * iv1;
            m0 = fmaxf(m0, fmaxf(f0[2 * nt], f0[2 * nt + 1]));
            m1 = fmaxf(m1, fmaxf(f1[2 * nt], f1[2 * nt + 1]));
        }
        m0 = fmaxf(m0, __shfl_xor_sync(0xffffffffu, m0, 1));
        m0 = fmaxf(m0, __shfl_xor_sync(0xffffffffu, m0, 2));
        m1 = fmaxf(m1, __shfl_xor_sync(0xffffffffu, m1, 1));
        m1 = fmaxf(m1, __shfl_xor_sync(0xffffffffu, m1, 2));
        float s0 = 0.f, s1 = 0.f;
#pragma unroll
        for (int i = 0; i < 16; i++) {
            f0[i] = __expf(f0[i] - m0); s0 += f0[i];
            f1[i] = __expf(f1[i] - m1); s1 += f1[i];
        }
        s0 += __shfl_xor_sync(0xffffffffu, s0, 1);
        s0 += __shfl_xor_sync(0xffffffffu, s0, 2);
        s1 += __shfl_xor_sync(0xffffffffu, s1, 1);
        s1 += __shfl_xor_sync(0xffffffffu, s1, 2);
        float sc0 = (p0 + r0 < PP) ? shm[r0] / s0 : 0.f;
        float sc1 = (p0 + r1 < PP) ? shm[r1] / s1 : 0.f;
#pragma unroll
        for (int i = 0; i < 16; i++) {
            int col = (i >> 1) * 8 + 2 * q + (i & 1);
            stsf(wst + (u32)(r0 * 65 + col) * 4, f0[i] * sc0);
            stsf(wst + (u32)(r1 * 65 + col) * 4, f1[i] * sc1);
        }
    }
    __syncthreads();

    if (t < 64) {   // wsum partial for this p-block
        float sm = 0.f;
        for (int pl = 0; pl < 128; pl++) sm += ldsf(wst + (u32)(pl * 65 + t) * 4);
        g_wsump[(n * NPB + pb) * KK + t] = sm;
    }
    if (pv) {       // packed bf16 hi|lo writeout (coalesced over p per k)
        for (int kk = 0; kk < 64; kk++) {
            float wv = ldsf(wst + (u32)(t * 65 + kk) * 4);
            u32 lp, hp = bsplit2(wv, 0.f, lp);
            g_wpk[((size_t)n * KK + kk) * PP + p] = (hp & 0xffffu) | (lp << 16);
        }
    }
}

// ---------------------------------------------------------------------------
// K3: term1 MMA D[c,k] = sum_p xn[c,p] * w[k,p]. Zero transposes on load.
// Block: n, 128-c tile. K=1600 in 25 stages of 64p. Grid (4, 48).
// ---------------------------------------------------------------------------
__global__ void __launch_bounds__(128)
k_vladgemm(const float* __restrict__ x, float* __restrict__ out) {
    extern __shared__ unsigned char dsm[];

    int t = threadIdx.x, wid = t >> 5, lane = t & 31;
    int ct = blockIdx.x, n = blockIdx.y;
    int c0 = ct * 128;
    const float* xb = x + (size_t)n * CC * PP;
    const u32* wb = g_wpk + (size_t)n * KK * PP;
    u32 base = smem_u32(dsm);
    u32 invo = base + XTRA;

    for (int i = t; i < PP; i += 128) stsf(invo + 4 * i, g_invn[n * PP + i]);

    int gr8 = lane & 7, sel = lane >> 3;
    int lrow = gr8 + (sel & 1) * 8;
    int lcolb = ((sel >> 1) * 8) * 2;
    u32 aoff = (u32)((wid * 32 + lrow) * RSTR + lcolb);
    u32 boff = (u32)(lrow * RSTR + lcolb);

    float acc[2][8][4];
#pragma unroll
    for (int mt = 0; mt < 2; mt++)
#pragma unroll
        for (int nt = 0; nt < 8; nt++)
#pragma unroll
            for (int r = 0; r < 4; r++) acc[mt][nt][r] = 0.f;
    __syncthreads();

    for (int st = 0; st < 25; st++) {
        int p0 = st * 64;
        // A fill: xn [128c x 64p] (natural layout, invn folded)
#pragma unroll
        for (int q = 0; q < 32; q++) {
            int e = t + q * 128;
            int c = e >> 5, p2 = e & 31;
            float2 v = *reinterpret_cast<const float2*>(&xb[(size_t)(c0 + c) * PP + p0 + 2 * p2]);
            float v0 = v.x * ldsf(invo + 4 * (p0 + 2 * p2));
            float v1 = v.y * ldsf(invo + 4 * (p0 + 2 * p2 + 1));
            u32 lp, hp = bsplit2(v0, v1, lp);
            u32 off = (u32)(c * RSTR + p2 * 4);
            sts32(base + AHI + off, hp);
            sts32(base + ALO + off, lp);
        }
        // B fill: w [64k x 64p] from packed hi|lo
#pragma unroll
        for (int q = 0; q < 16; q++) {
            int e = t + q * 128;
            int k = e >> 5, p2 = e & 31;
            uint2 u = *reinterpret_cast<const uint2*>(&wb[(size_t)k * PP + p0 + 2 * p2]);
            u32 off = (u32)(k * RSTR + p2 * 4);
            sts32(base + BHI + off, __byte_perm(u.x, u.y, 0x5410));
            sts32(base + BLO + off, __byte_perm(u.x, u.y, 0x7632));
        }
        __syncthreads();
#pragma unroll
        for (int kc = 0; kc < 4; kc++) {
            u32 ah[2][4], al[2][4];
            ldm4(base + AHI + aoff + kc * 32, ah[0]);
            ldm4(base + AHI + aoff + 16 * RSTR + kc * 32, ah[1]);
            ldm4(base + ALO + aoff + kc * 32, al[0]);
            ldm4(base + ALO + aoff + 16 * RSTR + kc * 32, al[1]);
#pragma unroll
            for (int j = 0; j < 4; j++) {
                u32 bh[4], bl[4];
                ldm4(base + BHI + boff + j * 16 * RSTR + kc * 32, bh);
                ldm4(base + BLO + boff + j * 16 * RSTR + kc * 32, bl);
#pragma unroll
                for (int mt = 0; mt < 2; mt++) {
                    mma_bf16(acc[mt][2 * j],     ah[mt], bh[0], bh[2]);
                    mma_bf16(acc[mt][2 * j],     ah[mt], bl[0], bl[2]);
                    mma_bf16(acc[mt][2 * j],     al[mt], bh[0], bh[2]);
                    mma_bf16(acc[mt][2 * j + 1], ah[mt], bh[1], bh[3]);
                    mma_bf16(acc[mt][2 * j + 1], ah[mt], bl[1], bl[3]);
                    mma_bf16(acc[mt][2 * j + 1], al[mt], bh[1], bh[3]);
                }
            }
        }
        __syncthreads();
    }

    // stage D[c,k] into smem [128][65], then transpose-write out[k][c]
    int gr = lane >> 2, q = lane & 3;
    u32 ds = base;
#pragma unroll
    for (int mt = 0; mt < 2; mt++) {
        int r0 = wid * 32 + mt * 16 + gr;
        int r1 = r0 + 8;
#pragma unroll
        for (int nt = 0; nt < 8; nt++) {
            int col = nt * 8 + 2 * q;
            stsf(ds + (u32)(r0 * 65 + col) * 4,     acc[mt][nt][0]);
            stsf(ds + (u32)(r0 * 65 + col + 1) * 4, acc[mt][nt][1]);
            stsf(ds + (u32)(r1 * 65 + col) * 4,     acc[mt][nt][2]);
            stsf(ds + (u32)(r1 * 65 + col + 1) * 4, acc[mt][nt][3]);
        }
    }
    __syncthreads();
    float* ob = out + (size_t)n * KK * CC;
    for (int kk = 0; kk < 64; kk++)
        ob[(size_t)kk * CC + c0 + t] = ldsf(ds + (u32)(t * 65 + kk) * 4);
}

// ---------------------------------------------------------------------------
// K4: vlad = term1 - wsum*centroid, intra-L2-norm per (n,k). 3072 blocks x 128.
// ---------------------------------------------------------------------------
__global__ void k_intranorm(float* __restrict__ out,
                            const float* __restrict__ cent) {
    int nk = blockIdx.x;
    int n = nk >> 6, k = nk & 63;
    int t = threadIdx.x;
    float wsv = 0.f;
#pragma unroll
    for (int pb = 0; pb < NPB; pb++) wsv += g_wsump[(n * NPB + pb) * KK + k];
    size_t base = (size_t)nk * CC;
    const float* cb = cent + (size_t)k * CC;

    float v[4];
    float ss = 0.f;
#pragma unroll
    for (int q = 0; q < 4; q++) {
        int c = t + 128 * q;
        v[q] = out[base + c] - wsv * cb[c];
        ss = fmaf(v[q], v[q], ss);
    }
#pragma unroll
    for (int o = 16; o > 0; o >>= 1) ss += __shfl_xor_sync(0xffffffffu, ss, o);
    __shared__ float sred[4];
    if ((t & 31) == 0) sred[t >> 5] = ss;
    __syncthreads();
    float tot = sred[0] + sred[1] + sred[2] + sred[3];
    float invv = 1.f / fmaxf(sqrtf(tot), EPSV);
#pragma unroll
    for (int q = 0; q < 4; q++) out[base + t + 128 * q] = v[q] * invv;
    if (t == 0) g_knss[nk] = tot * invv * invv;
}

// ---------------------------------------------------------------------------
// K5: global L2 norm per n. Grid (48, 16), 2048 elems per block.
// ---------------------------------------------------------------------------
__global__ void k_globalnorm(float* __restrict__ out) {
    int n = blockIdx.x, t = threadIdx.x;
    float gs = 0.f;
#pragma unroll
    for (int i = 0; i < KK; i++) gs += g_knss[n * KK + i];
    float sc = 1.f / fmaxf(sqrtf(gs), EPSV);
    size_t base = (size_t)n * KK * CC + (size_t)blockIdx.y * 2048;
#pragma unroll
    for (int q = 0; q < 8; q++) out[base + t + 256 * q] *= sc;
}

// ---------------------------------------------------------------------------
extern "C" void kernel_launch(void* const* d_in, const int* in_sizes, int n_in,
                              void* d_out, int out_size) {
    const float* x  = (const float*)d_in[0];   // [48,512,40,40]
    const float* cw = (const float*)d_in[1];   // [64,512]
    const float* aw = (const float*)d_in[2];   // [1,512]
    const float* ab = (const float*)d_in[3];   // [1]
    const float* ct = (const float*)d_in[4];   // [64,512]
    float* out = (float*)d_out;                // [48, 32768]

    cudaFuncSetAttribute(k_assign,   cudaFuncAttributeMaxDynamicSharedMemorySize, SMEM_K2);
    cudaFuncSetAttribute(k_vladgemm, cudaFuncAttributeMaxDynamicSharedMemorySize, SMEM_K3);

    k_assign<<<dim3(13, 48), 128, SMEM_K2>>>(x, cw, aw, ab);
    k_vladgemm<<<dim3(4, 48), 128, SMEM_K3>>>(x, out);
    k_intranorm<<<NB * KK, 128>>>(out, ct);
    k_globalnorm<<<dim3(48, 16), 256>>>(out);
}

// round 14
// speedup vs baseline: 2.2264x; 1.4300x over previous
#include <cuda_runtime.h>
#include <cuda_bf16.h>
#include <math.h>

#define NB 48
#define CC 512
#define PP 1600
#define KK 64
#define EPSV 1e-12f
#define NPB 13

typedef unsigned long long ull;
typedef unsigned int u32;
typedef unsigned short u16;

// Scratch (device globals; no allocations allowed).
__device__ __align__(16) u16   g_xhi[NB * CC * PP + 128];   // bf16 hi plane of raw x
__device__ __align__(16) u16   g_xlo[NB * CC * PP + 128];   // bf16 lo (residual) plane
__device__ __align__(16) u16   g_cwhi[KK * CC];             // conv_w hi plane
__device__ __align__(16) u16   g_cwlo[KK * CC];             // conv_w lo plane
__device__ __align__(16) u32   g_wpk[NB * KK * PP];         // w*invn packed bf16 hi|lo
__device__ __align__(16) float g_invn[NB * PP];
__device__ __align__(16) float g_hmp[NB * PP];
__device__ __align__(16) float g_wsump[NB * NPB * KK];      // per-pblock raw wsum
__device__ __align__(16) float g_t1[2 * NB * KK * CC];      // term1 partials (2 p-splits)
__device__ __align__(16) float g_knss[NB * KK];

// ---------------- low-level helpers ----------------
__device__ __forceinline__ u32 smem_u32(const void* p) {
    return (u32)__cvta_generic_to_shared(p);
}
__device__ __forceinline__ void sts32(u32 a, u32 v) {
    asm volatile("st.shared.b32 [%0], %1;" :: "r"(a), "r"(v));
}
__device__ __forceinline__ void stsf(u32 a, float v) {
    asm volatile("st.shared.f32 [%0], %1;" :: "r"(a), "f"(v));
}
__device__ __forceinline__ float ldsf(u32 a) {
    float v; asm volatile("ld.shared.f32 %0, [%1];" : "=f"(v) : "r"(a)); return v;
}
#define CPA16(s, g) asm volatile("cp.async.cg.shared.global [%0], [%1], 16;" :: "r"(s), "l"(g))
#define CPWAIT() asm volatile("cp.async.commit_group;\n\tcp.async.wait_group 0;" ::: "memory")

// hp = {bf16(v1), bf16(v0)} (v0 low half); lp = residual plane likewise.
__device__ __forceinline__ u32 bsplit2(float v0, float v1, u32& lp) {
    u32 hp;
    asm("cvt.rn.bf16x2.f32 %0, %1, %2;" : "=r"(hp) : "f"(v1), "f"(v0));
    float r0 = v0 - __uint_as_float(hp << 16);
    float r1 = v1 - __uint_as_float(hp & 0xffff0000u);
    asm("cvt.rn.bf16x2.f32 %0, %1, %2;" : "=r"(lp) : "f"(r1), "f"(r0));
    return hp;
}
__device__ __forceinline__ void ldm4(u32 a, u32* r) {
    asm volatile("ldmatrix.sync.aligned.m8n8.x4.shared.b16 {%0,%1,%2,%3}, [%4];"
        : "=r"(r[0]), "=r"(r[1]), "=r"(r[2]), "=r"(r[3]) : "r"(a));
}
__device__ __forceinline__ void ldm4t(u32 a, u32* r) {
    asm volatile("ldmatrix.sync.aligned.m8n8.x4.trans.shared.b16 {%0,%1,%2,%3}, [%4];"
        : "=r"(r[0]), "=r"(r[1]), "=r"(r[2]), "=r"(r[3]) : "r"(a));
}
__device__ __forceinline__ void mma_bf16(float* d, const u32* a, u32 b0, u32 b1) {
    asm volatile("mma.sync.aligned.m16n8k16.row.col.f32.bf16.bf16.f32 "
        "{%0,%1,%2,%3}, {%4,%5,%6,%7}, {%8,%9}, {%0,%1,%2,%3};"
        : "+f"(d[0]), "+f"(d[1]), "+f"(d[2]), "+f"(d[3])
        : "r"(a[0]), "r"(a[1]), "r"(a[2]), "r"(a[3]), "r"(b0), "r"(b1));
}

// ---------------------------------------------------------------------------
// K1: per-pixel channel stats -> invn, hmp. One coalesced pass over x.
// ---------------------------------------------------------------------------
__global__ void k_pixstats(const float* __restrict__ x,
                           const float* __restrict__ aw,
                           const float* __restrict__ ab) {
    __shared__ float saw[CC];
    int t = threadIdx.x;
    for (int i = t; i < CC; i += 256) saw[i] = aw[i];
    __syncthreads();

    int pix = blockIdx.x * 256 + t;              // 76800 = 300*256
    int n = pix / PP;
    int p = pix - n * PP;
    const float* xp = x + (size_t)n * CC * PP + p;

    float ss = 0.f, av = 0.f;
#pragma unroll 8
    for (int c = 0; c < CC; c++) {
        float v = xp[(size_t)c * PP];
        ss = fmaf(v, v, ss);
        float r = v > 0.f ? v : 0.f;
        av = fmaf(r, saw[c], av);
    }
    float hm = av + ab[0];
    g_hmp[pix] = hm > 0.f ? hm : 0.f;
    g_invn[pix] = 1.f / fmaxf(sqrtf(ss), EPSV);
}

// ---------------------------------------------------------------------------
// K1b: convert raw x (and cw) to bf16 hi/lo planes. Vectorized float4.
// Grid 38432 x 256: blocks [0,38400) cover x, [38400,38432) cover cw.
// ---------------------------------------------------------------------------
__global__ void k_convert(const float* __restrict__ x,
                          const float* __restrict__ cw) {
    int bid = blockIdx.x, t = threadIdx.x;
    if (bid < 38400) {
        size_t base = (size_t)bid * 1024 + t * 4;
        float4 v = *reinterpret_cast<const float4*>(x + base);
        u32 l0, l1;
        u32 h0 = bsplit2(v.x, v.y, l0);
        u32 h1 = bsplit2(v.z, v.w, l1);
        *reinterpret_cast<uint2*>(&g_xhi[base]) = make_uint2(h0, h1);
        *reinterpret_cast<uint2*>(&g_xlo[base]) = make_uint2(l0, l1);
    } else {
        int base = (bid - 38400) * 1024 + t * 4;
        float4 v = *reinterpret_cast<const float4*>(cw + base);
        u32 l0, l1;
        u32 h0 = bsplit2(v.x, v.y, l0);
        u32 h1 = bsplit2(v.z, v.w, l1);
        *reinterpret_cast<uint2*>(&g_cwhi[base]) = make_uint2(h0, h1);
        *reinterpret_cast<uint2*>(&g_cwlo[base]) = make_uint2(l0, l1);
    }
}

// K2 smem layout (bytes): A planes [64c][272B], B planes [64k][144B]
#define K2_AP0 0
#define K2_AP1 17408
#define K2_BP0 34816
#define K2_BP1 44032
#define SMEM_K2 53248
// K3 smem: A [128c][144B], B [64k][144B]
#define K3_AP0 0
#define K3_AP1 18432
#define K3_BP0 36864
#define K3_BP1 46080
#define SMEM_K3 55296

// ---------------------------------------------------------------------------
// K2: logits MMA D[p,k] from planes (trans-ldmatrix A) + softmax + w' packing.
// Grid (13, 48), 128 threads, 8 stages of 64c. cp.async copy fills.
// ---------------------------------------------------------------------------
__global__ void __launch_bounds__(128) k_assign() {
    extern __shared__ unsigned char dsm[];
    __shared__ float sinv[128], shm[128];

    int t = threadIdx.x, wid = t >> 5, lane = t & 31;
    int n = blockIdx.y, pb = blockIdx.x;
    int p0 = pb * 128;
    u32 base = smem_u32(dsm);
    const u16* xh = g_xhi + (size_t)n * CC * PP;
    const u16* xl = g_xlo + (size_t)n * CC * PP;

    int p = p0 + t;
    bool pv = p < PP;
    sinv[t] = pv ? g_invn[n * PP + p] : 0.f;
    shm[t]  = pv ? g_hmp[n * PP + p] : 0.f;

    int gr8 = lane & 7, sel = lane >> 3;
    // A (trans): smem rows = c, cols = p
    u32 aoff0 = (u32)((gr8 + (sel >> 1) * 8) * 272 + ((sel & 1) * 8 + wid * 32) * 2);
    // B (non-trans): smem rows = k, cols = c
    u32 boff = (u32)((gr8 + (sel & 1) * 8) * 144 + ((sel >> 1) * 8) * 2);

    float acc[2][8][4];
#pragma unroll
    for (int mt = 0; mt < 2; mt++)
#pragma unroll
        for (int nt = 0; nt < 8; nt++)
#pragma unroll
            for (int r = 0; r < 4; r++) acc[mt][nt][r] = 0.f;
    __syncthreads();

    int ar = t >> 4, acs = (t & 15) * 8;     // A: 8 rows/iter, 16B segs
    int br = t >> 3, bcs = (t & 7) * 8;      // B: 16 rows/iter

    for (int st = 0; st < 8; st++) {
        int c0 = st * 64;
#pragma unroll
        for (int it = 0; it < 8; it++) {
            int row = ar + it * 8;
            size_t g = (size_t)(c0 + row) * PP + p0 + acs;
            u32 so = (u32)(row * 272 + acs * 2);
            CPA16(base + K2_AP0 + so, xh + g);
            CPA16(base + K2_AP1 + so, xl + g);
        }
#pragma unroll
        for (int it = 0; it < 4; it++) {
            int row = br + it * 16;
            int g = row * CC + c0 + bcs;
            u32 so = (u32)(row * 144 + bcs * 2);
            CPA16(base + K2_BP0 + so, g_cwhi + g);
            CPA16(base + K2_BP1 + so, g_cwlo + g);
        }
        CPWAIT();
        __syncthreads();
#pragma unroll
        for (int kc = 0; kc < 4; kc++) {
            u32 ah[2][4], al[2][4];
            u32 aA = base + K2_AP0 + aoff0 + (u32)kc * 4352;
            ldm4t(aA, ah[0]); ldm4t(aA + 32, ah[1]);
            ldm4t(aA + (K2_AP1 - K2_AP0), al[0]); ldm4t(aA + (K2_AP1 - K2_AP0) + 32, al[1]);
#pragma unroll
            for (int j = 0; j < 4; j++) {
                u32 bh[4], bl[4];
                u32 aB = base + K2_BP0 + boff + (u32)j * 2304 + (u32)kc * 32;
                ldm4(aB, bh);
                ldm4(aB + (K2_BP1 - K2_BP0), bl);
#pragma unroll
                for (int mt = 0; mt < 2; mt++) {
                    mma_bf16(acc[mt][2 * j],     ah[mt], bh[0], bh[2]);
                    mma_bf16(acc[mt][2 * j],     ah[mt], bl[0], bl[2]);
                    mma_bf16(acc[mt][2 * j],     al[mt], bh[0], bh[2]);
                    mma_bf16(acc[mt][2 * j + 1], ah[mt], bh[1], bh[3]);
                    mma_bf16(acc[mt][2 * j + 1], ah[mt], bl[1], bl[3]);
                    mma_bf16(acc[mt][2 * j + 1], al[mt], bh[1], bh[3]);
                }
            }
        }
        __syncthreads();
    }

    // softmax over k on fragments; stage raw w [128p][65] f32 (overlays A planes)
    int gr = lane >> 2, q = lane & 3;
    u32 wst = base;
#pragma unroll
    for (int mt = 0; mt < 2; mt++) {
        int r0 = wid * 32 + mt * 16 + gr;
        int r1 = r0 + 8;
        float iv0 = sinv[r0], iv1 = sinv[r1];
        float f0[16], f1[16];
        float m0 = -1e30f, m1 = -1e30f;
#pragma unroll
        for (int nt = 0; nt < 8; nt++) {
            f0[2 * nt]     = acc[mt][nt][0] * iv0;
            f0[2 * nt + 1] = acc[mt][nt][1] * iv0;
            f1[2 * nt]     = acc[mt][nt][2] * iv1;
            f1[2 * nt + 1] = acc[mt][nt][3] * iv1;
            m0 = fmaxf(m0, fmaxf(f0[2 * nt], f0[2 * nt + 1]));
            m1 = fmaxf(m1, fmaxf(f1[2 * nt], f1[2 * nt + 1]));
        }
        m0 = fmaxf(m0, __shfl_xor_sync(0xffffffffu, m0, 1));
        m0 = fmaxf(m0, __shfl_xor_sync(0xffffffffu, m0, 2));
        m1 = fmaxf(m1, __shfl_xor_sync(0xffffffffu, m1, 1));
        m1 = fmaxf(m1, __shfl_xor_sync(0xffffffffu, m1, 2));
        float s0 = 0.f, s1 = 0.f;
#pragma unroll
        for (int i = 0; i < 16; i++) {
            f0[i] = __expf(f0[i] - m0); s0 += f0[i];
            f1[i] = __expf(f1[i] - m1); s1 += f1[i];
        }
        s0 += __shfl_xor_sync(0xffffffffu, s0, 1);
        s0 += __shfl_xor_sync(0xffffffffu, s0, 2);
        s1 += __shfl_xor_sync(0xffffffffu, s1, 1);
        s1 += __shfl_xor_sync(0xffffffffu, s1, 2);
        float sc0 = (p0 + r0 < PP) ? shm[r0] / s0 : 0.f;
        float sc1 = (p0 + r1 < PP) ? shm[r1] / s1 : 0.f;
#pragma unroll
        for (int i = 0; i < 16; i++) {
            int col = (i >> 1) * 8 + 2 * q + (i & 1);
            stsf(wst + (u32)(r0 * 65 + col) * 4, f0[i] * sc0);
            stsf(wst + (u32)(r1 * 65 + col) * 4, f1[i] * sc1);
        }
    }
    __syncthreads();

    if (t < 64) {   // raw wsum partial for this p-block
        float sm = 0.f;
        for (int pl = 0; pl < 128; pl++) sm += ldsf(wst + (u32)(pl * 65 + t) * 4);
        g_wsump[(n * NPB + pb) * KK + t] = sm;
    }
    if (pv) {       // pack w' = w * invn as bf16 hi|lo
        float iv = sinv[t];
        for (int kk = 0; kk < 64; kk++) {
            float wv = ldsf(wst + (u32)(t * 65 + kk) * 4) * iv;
            u32 lp, hp = bsplit2(wv, 0.f, lp);
            g_wpk[((size_t)n * KK + kk) * PP + p] = (hp & 0xffffu) | (lp << 16);
        }
    }
}

// ---------------------------------------------------------------------------
// K3: term1 partial MMA D[c,k] = sum_p x[c,p] * w'[k,p]. Pure copy fills.
// Grid (4, 48, 2): p-split halves (13/12 stages of 64p).
// ---------------------------------------------------------------------------
__global__ void __launch_bounds__(128) k_vladgemm() {
    extern __shared__ unsigned char dsm[];

    int t = threadIdx.x, wid = t >> 5, lane = t & 31;
    int ct = blockIdx.x, n = blockIdx.y, sp = blockIdx.z;
    int c0 = ct * 128;
    int nst = sp ? 12 : 13;
    int stb = sp * 13;
    const u16* xh = g_xhi + (size_t)n * CC * PP;
    const u16* xl = g_xlo + (size_t)n * CC * PP;
    const u32* wb = g_wpk + (size_t)n * KK * PP;
    u32 base = smem_u32(dsm);

    int gr8 = lane & 7, sel = lane >> 3;
    int lrow = gr8 + (sel & 1) * 8;
    int lcolb = (sel >> 1) * 16;
    u32 aoff = (u32)((wid * 32 + lrow) * 144 + lcolb);
    u32 boff = (u32)(lrow * 144 + lcolb);

    float acc[2][8][4];
#pragma unroll
    for (int mt = 0; mt < 2; mt++)
#pragma unroll
        for (int nt = 0; nt < 8; nt++)
#pragma unroll
            for (int r = 0; r < 4; r++) acc[mt][nt][r] = 0.f;
    __syncthreads();

    int ar = t >> 3, acs = (t & 7) * 8;

    for (int st = 0; st < nst; st++) {
        int p0 = (stb + st) * 64;
#pragma unroll
        for (int it = 0; it < 8; it++) {
            int row = ar + it * 16;
            size_t g = (size_t)(c0 + row) * PP + p0 + acs;
            u32 so = (u32)(row * 144 + acs * 2);
            CPA16(base + K3_AP0 + so, xh + g);
            CPA16(base + K3_AP1 + so, xl + g);
        }
#pragma unroll
        for (int q = 0; q < 16; q++) {
            int e = t + q * 128;
            int k = e >> 5, p2 = e & 31;
            uint2 u = *reinterpret_cast<const uint2*>(&wb[(size_t)k * PP + p0 + 2 * p2]);
            u32 off = (u32)(k * 144 + p2 * 4);
            sts32(base + K3_BP0 + off, __byte_perm(u.x, u.y, 0x5410));
            sts32(base + K3_BP1 + off, __byte_perm(u.x, u.y, 0x7632));
        }
        CPWAIT();
        __syncthreads();
#pragma unroll
        for (int kc = 0; kc < 4; kc++) {
            u32 ah[2][4], al[2][4];
            u32 aA = base + K3_AP0 + aoff + (u32)kc * 32;
            ldm4(aA, ah[0]); ldm4(aA + 2304, ah[1]);
            ldm4(aA + (K3_AP1 - K3_AP0), al[0]); ldm4(aA + (K3_AP1 - K3_AP0) + 2304, al[1]);
#pragma unroll
            for (int j = 0; j < 4; j++) {
                u32 bh[4], bl[4];
                u32 aB = base + K3_BP0 + boff + (u32)j * 2304 + (u32)kc * 32;
                ldm4(aB, bh);
                ldm4(aB + (K3_BP1 - K3_BP0), bl);
#pragma unroll
                for (int mt = 0; mt < 2; mt++) {
                    mma_bf16(acc[mt][2 * j],     ah[mt], bh[0], bh[2]);
                    mma_bf16(acc[mt][2 * j],     ah[mt], bl[0], bl[2]);
                    mma_bf16(acc[mt][2 * j],     al[mt], bh[0], bh[2]);
                    mma_bf16(acc[mt][2 * j + 1], ah[mt], bh[1], bh[3]);
                    mma_bf16(acc[mt][2 * j + 1], ah[mt], bl[1], bl[3]);
                    mma_bf16(acc[mt][2 * j + 1], al[mt], bh[1], bh[3]);
                }
            }
        }
        __syncthreads();
    }

    // stage D[c,k] [128][65] f32, transpose-write to g_t1 partial
    int gr = lane >> 2, q = lane & 3;
    u32 ds = base;
#pragma unroll
    for (int mt = 0; mt < 2; mt++) {
        int r0 = wid * 32 + mt * 16 + gr;
        int r1 = r0 + 8;
#pragma unroll
        for (int nt = 0; nt < 8; nt++) {
            int col = nt * 8 + 2 * q;
            stsf(ds + (u32)(r0 * 65 + col) * 4,     acc[mt][nt][0]);
            stsf(ds + (u32)(r0 * 65 + col + 1) * 4, acc[mt][nt][1]);
            stsf(ds + (u32)(r1 * 65 + col) * 4,     acc[mt][nt][2]);
            stsf(ds + (u32)(r1 * 65 + col + 1) * 4, acc[mt][nt][3]);
        }
    }
    __syncthreads();
    float* ob = g_t1 + ((size_t)sp * NB + n) * KK * CC;
    for (int kk = 0; kk < 64; kk++)
        ob[(size_t)kk * CC + c0 + t] = ldsf(ds + (u32)(t * 65 + kk) * 4);
}

// ---------------------------------------------------------------------------
// K4: vlad = sum(term1 partials) - wsum*centroid, intra-L2-norm per (n,k).
// ---------------------------------------------------------------------------
__global__ void k_intranorm(float* __restrict__ out,
                            const float* __restrict__ cent) {
    int nk = blockIdx.x;
    int n = nk >> 6, k = nk & 63;
    int t = threadIdx.x;
    float wsv = 0.f;
#pragma unroll
    for (int pb = 0; pb < NPB; pb++) wsv += g_wsump[(n * NPB + pb) * KK + k];
    size_t base = (size_t)nk * CC;
    const float* cb = cent + (size_t)k * CC;
    const size_t TOT = (size_t)NB * KK * CC;

    float v[4];
    float ss = 0.f;
#pragma unroll
    for (int q = 0; q < 4; q++) {
        int c = t + 128 * q;
        float tv = g_t1[base + c] + g_t1[TOT + base + c];
        v[q] = tv - wsv * cb[c];
        ss = fmaf(v[q], v[q], ss);
    }
#pragma unroll
    for (int o = 16; o > 0; o >>= 1) ss += __shfl_xor_sync(0xffffffffu, ss, o);
    __shared__ float sred[4];
    if ((t & 31) == 0) sred[t >> 5] = ss;
    __syncthreads();
    float tot = sred[0] + sred[1] + sred[2] + sred[3];
    float invv = 1.f / fmaxf(sqrtf(tot), EPSV);
#pragma unroll
    for (int q = 0; q < 4; q++) out[base + t + 128 * q] = v[q] * invv;
    if (t == 0) g_knss[nk] = tot * invv * invv;
}

// ---------------------------------------------------------------------------
// K5: global L2 norm per n. Grid (48, 16), 2048 elems per block.
// ---------------------------------------------------------------------------
__global__ void k_globalnorm(float* __restrict__ out) {
    int n = blockIdx.x, t = threadIdx.x;
    float gs = 0.f;
#pragma unroll
    for (int i = 0; i < KK; i++) gs += g_knss[n * KK + i];
    float sc = 1.f / fmaxf(sqrtf(gs), EPSV);
    size_t base = (size_t)n * KK * CC + (size_t)blockIdx.y * 2048;
#pragma unroll
    for (int q = 0; q < 8; q++) out[base + t + 256 * q] *= sc;
}

// ---------------------------------------------------------------------------
extern "C" void kernel_launch(void* const* d_in, const int* in_sizes, int n_in,
                              void* d_out, int out_size) {
    const float* x  = (const float*)d_in[0];   // [48,512,40,40]
    const float* cw = (const float*)d_in[1];   // [64,512]
    const float* aw = (const float*)d_in[2];   // [1,512]
    const float* ab = (const float*)d_in[3];   // [1]
    const float* ct = (const float*)d_in[4];   // [64,512]
    float* out = (float*)d_out;                // [48, 32768]

    cudaFuncSetAttribute(k_assign,   cudaFuncAttributeMaxDynamicSharedMemorySize, SMEM_K2);
    cudaFuncSetAttribute(k_vladgemm, cudaFuncAttributeMaxDynamicSharedMemorySize, SMEM_K3);

    k_pixstats<<<300, 256>>>(x, aw, ab);
    k_convert<<<38432, 256>>>(x, cw);
    k_assign<<<dim3(13, 48), 128, SMEM_K2>>>();
    k_vladgemm<<<dim3(4, 48, 2), 128, SMEM_K3>>>();
    k_intranorm<<<NB * KK, 128>>>(out, ct);
    k_globalnorm<<<dim3(48, 16), 256>>>(out);
}

// round 16
// speedup vs baseline: 2.4647x; 1.1070x over previous
#include <cuda_runtime.h>
#include <cuda_bf16.h>
#include <math.h>

#define NB 48
#define CC 512
#define PP 1600
#define KK 64
#define EPSV 1e-12f
#define NPB 13

typedef unsigned long long ull;
typedef unsigned int u32;
typedef unsigned short u16;

// Scratch (device globals; no allocations allowed).
__device__ __align__(16) u16   g_xhi[NB * CC * PP + 128];   // bf16 hi plane of raw x
__device__ __align__(16) u16   g_xlo[NB * CC * PP + 128];   // bf16 lo (residual) plane
__device__ __align__(16) u16   g_cwhi[KK * CC];             // conv_w hi plane
__device__ __align__(16) u16   g_cwlo[KK * CC];             // conv_w lo plane
__device__ __align__(16) u16   g_whi[NB * KK * PP + 128];   // w*invn hi plane
__device__ __align__(16) u16   g_wlo[NB * KK * PP + 128];   // w*invn lo plane
__device__ __align__(16) float g_invn[NB * PP];
__device__ __align__(16) float g_hmp[NB * PP];
__device__ __align__(16) float g_wsump[NB * NPB * KK];      // per-pblock raw wsum
__device__ __align__(16) float g_t1[2 * NB * KK * CC];      // term1 partials (2 p-splits)
__device__ __align__(16) float g_knss[NB * KK];

// ---------------- low-level helpers ----------------
__device__ __forceinline__ u32 smem_u32(const void* p) {
    return (u32)__cvta_generic_to_shared(p);
}
__device__ __forceinline__ void stsf(u32 a, float v) {
    asm volatile("st.shared.f32 [%0], %1;" :: "r"(a), "f"(v));
}
__device__ __forceinline__ float ldsf(u32 a) {
    float v; asm volatile("ld.shared.f32 %0, [%1];" : "=f"(v) : "r"(a)); return v;
}
#define CPA16(s, g) asm volatile("cp.async.cg.shared.global [%0], [%1], 16;" :: "r"(s), "l"(g))
#define CPCOMMIT()  asm volatile("cp.async.commit_group;" ::: "memory")
#define CPWAIT1()   asm volatile("cp.async.wait_group 1;" ::: "memory")
#define CPWAIT0()   asm volatile("cp.async.wait_group 0;" ::: "memory")

// hp = {bf16(v1), bf16(v0)} (v0 low half); lp = residual plane likewise.
__device__ __forceinline__ u32 bsplit2(float v0, float v1, u32& lp) {
    u32 hp;
    asm("cvt.rn.bf16x2.f32 %0, %1, %2;" : "=r"(hp) : "f"(v1), "f"(v0));
    float r0 = v0 - __uint_as_float(hp << 16);
    float r1 = v1 - __uint_as_float(hp & 0xffff0000u);
    asm("cvt.rn.bf16x2.f32 %0, %1, %2;" : "=r"(lp) : "f"(r1), "f"(r0));
    return hp;
}
__device__ __forceinline__ void ldm4(u32 a, u32* r) {
    asm volatile("ldmatrix.sync.aligned.m8n8.x4.shared.b16 {%0,%1,%2,%3}, [%4];"
        : "=r"(r[0]), "=r"(r[1]), "=r"(r[2]), "=r"(r[3]) : "r"(a));
}
__device__ __forceinline__ void ldm4t(u32 a, u32* r) {
    asm volatile("ldmatrix.sync.aligned.m8n8.x4.trans.shared.b16 {%0,%1,%2,%3}, [%4];"
        : "=r"(r[0]), "=r"(r[1]), "=r"(r[2]), "=r"(r[3]) : "r"(a));
}
__device__ __forceinline__ void mma_bf16(float* d, const u32* a, u32 b0, u32 b1) {
    asm volatile("mma.sync.aligned.m16n8k16.row.col.f32.bf16.bf16.f32 "
        "{%0,%1,%2,%3}, {%4,%5,%6,%7}, {%8,%9}, {%0,%1,%2,%3};"
        : "+f"(d[0]), "+f"(d[1]), "+f"(d[2]), "+f"(d[3])
        : "r"(a[0]), "r"(a[1]), "r"(a[2]), "r"(a[3]), "r"(b0), "r"(b1));
}

// ---------------------------------------------------------------------------
// K1: fused per-pixel stats + bf16 hi/lo plane conversion (single x pass).
// ---------------------------------------------------------------------------
__global__ void k_pixstats(const float* __restrict__ x,
                           const float* __restrict__ aw,
                           const float* __restrict__ ab) {
    __shared__ float saw[CC];
    int t = threadIdx.x;
    for (int i = t; i < CC; i += 256) saw[i] = aw[i];
    __syncthreads();

    int pix = blockIdx.x * 256 + t;              // 76800 = 300*256
    int n = pix / PP;
    int p = pix - n * PP;
    size_t xo = (size_t)n * CC * PP + p;
    const float* xp = x + xo;

    float ss = 0.f, av = 0.f;
#pragma unroll 8
    for (int c = 0; c < CC; c++) {
        float v = xp[(size_t)c * PP];
        ss = fmaf(v, v, ss);
        float r = v > 0.f ? v : 0.f;
        av = fmaf(r, saw[c], av);
        __nv_bfloat16 bh = __float2bfloat16_rn(v);
        float res = v - __bfloat162float(bh);
        g_xhi[xo + (size_t)c * PP] = __bfloat16_as_ushort(bh);
        g_xlo[xo + (size_t)c * PP] = __bfloat16_as_ushort(__float2bfloat16_rn(res));
    }
    float hm = av + ab[0];
    g_hmp[pix] = hm > 0.f ? hm : 0.f;
    g_invn[pix] = 1.f / fmaxf(sqrtf(ss), EPSV);
}

// ---------------------------------------------------------------------------
// K1b: convert cw to bf16 hi/lo planes. 32 blocks x 256 thr x 4 elems.
// ---------------------------------------------------------------------------
__global__ void k_cwconv(const float* __restrict__ cw) {
    int base = blockIdx.x * 1024 + threadIdx.x * 4;
    float4 v = *reinterpret_cast<const float4*>(cw + base);
    u32 l0, l1;
    u32 h0 = bsplit2(v.x, v.y, l0);
    u32 h1 = bsplit2(v.z, v.w, l1);
    *reinterpret_cast<uint2*>(&g_cwhi[base]) = make_uint2(h0, h1);
    *reinterpret_cast<uint2*>(&g_cwlo[base]) = make_uint2(l0, l1);
}

// K2 buffer layout (bytes): A planes [64c][272B], B planes [64k][144B]
#define K2_AP0 0
#define K2_AP1 17408
#define K2_BP0 34816
#define K2_BP1 44032
#define K2_BUF 53248
#define SMEM_K2 (2 * K2_BUF)
// K3 buffer: A [128c][144B], B [64k][144B]
#define K3_AP0 0
#define K3_AP1 18432
#define K3_BP0 36864
#define K3_BP1 46080
#define K3_BUF 55296
#define SMEM_K3 (2 * K3_BUF)

__device__ __forceinline__ void k2_fill(u32 bb, int c0, int p0,
                                        const u16* xh, const u16* xl, int t) {
    int ar = t >> 4, acs = (t & 15) * 8;
#pragma unroll
    for (int it = 0; it < 8; it++) {
        int row = ar + it * 8;
        size_t g = (size_t)(c0 + row) * PP + p0 + acs;
        u32 so = (u32)(row * 272 + acs * 2);
        CPA16(bb + K2_AP0 + so, xh + g);
        CPA16(bb + K2_AP1 + so, xl + g);
    }
    int br = t >> 3, bcs = (t & 7) * 8;
#pragma unroll
    for (int it = 0; it < 4; it++) {
        int row = br + it * 16;
        int g = row * CC + c0 + bcs;
        u32 so = (u32)(row * 144 + bcs * 2);
        CPA16(bb + K2_BP0 + so, g_cwhi + g);
        CPA16(bb + K2_BP1 + so, g_cwlo + g);
    }
    CPCOMMIT();
}

// ---------------------------------------------------------------------------
// K2: logits MMA D[p,k] + softmax + w' plane writeout. Double-buffered.
// Grid (13, 48), 128 threads, 8 stages of 64c.
// ---------------------------------------------------------------------------
__global__ void __launch_bounds__(128) k_assign() {
    extern __shared__ unsigned char dsm[];
    __shared__ float sinv[128], shm[128];

    int t = threadIdx.x, wid = t >> 5, lane = t & 31;
    int n = blockIdx.y, pb = blockIdx.x;
    int p0 = pb * 128;
    u32 base = smem_u32(dsm);
    const u16* xh = g_xhi + (size_t)n * CC * PP;
    const u16* xl = g_xlo + (size_t)n * CC * PP;

    int p = p0 + t;
    bool pv = p < PP;
    sinv[t] = pv ? g_invn[n * PP + p] : 0.f;
    shm[t]  = pv ? g_hmp[n * PP + p] : 0.f;

    int gr8 = lane & 7, sel = lane >> 3;
    u32 aoff0 = (u32)((gr8 + (sel >> 1) * 8) * 272 + ((sel & 1) * 8 + wid * 32) * 2);
    u32 boff = (u32)((gr8 + (sel & 1) * 8) * 144 + ((sel >> 1) * 8) * 2);

    float acc[2][8][4];
#pragma unroll
    for (int mt = 0; mt < 2; mt++)
#pragma unroll
        for (int nt = 0; nt < 8; nt++)
#pragma unroll
            for (int r = 0; r < 4; r++) acc[mt][nt][r] = 0.f;
    __syncthreads();

    k2_fill(base, 0, p0, xh, xl, t);
    for (int st = 0; st < 8; st++) {
        if (st + 1 < 8) {
            k2_fill(base + ((st + 1) & 1) * K2_BUF, (st + 1) * 64, p0, xh, xl, t);
            CPWAIT1();
        } else {
            CPWAIT0();
        }
        __syncthreads();
        u32 bb = base + (st & 1) * K2_BUF;
#pragma unroll
        for (int kc = 0; kc < 4; kc++) {
            u32 ah[2][4], al[2][4];
            u32 aA = bb + K2_AP0 + aoff0 + (u32)kc * 4352;
            ldm4t(aA, ah[0]); ldm4t(aA + 32, ah[1]);
            ldm4t(aA + (K2_AP1 - K2_AP0), al[0]); ldm4t(aA + (K2_AP1 - K2_AP0) + 32, al[1]);
#pragma unroll
            for (int j = 0; j < 4; j++) {
                u32 bh[4], bl[4];
                u32 aB = bb + K2_BP0 + boff + (u32)j * 2304 + (u32)kc * 32;
                ldm4(aB, bh);
                ldm4(aB + (K2_BP1 - K2_BP0), bl);
#pragma unroll
                for (int mt = 0; mt < 2; mt++) {
                    mma_bf16(acc[mt][2 * j],     ah[mt], bh[0], bh[2]);
                    mma_bf16(acc[mt][2 * j],     ah[mt], bl[0], bl[2]);
                    mma_bf16(acc[mt][2 * j],     al[mt], bh[0], bh[2]);
                    mma_bf16(acc[mt][2 * j + 1], ah[mt], bh[1], bh[3]);
                    mma_bf16(acc[mt][2 * j + 1], ah[mt], bl[1], bl[3]);
                    mma_bf16(acc[mt][2 * j + 1], al[mt], bh[1], bh[3]);
                }
            }
        }
        __syncthreads();
    }

    // softmax over k on fragments; stage raw w [128p][65] f32 in buffer 0
    int gr = lane >> 2, q = lane & 3;
    u32 wst = base;
#pragma unroll
    for (int mt = 0; mt < 2; mt++) {
        int r0 = wid * 32 + mt * 16 + gr;
        int r1 = r0 + 8;
        float iv0 = sinv[r0], iv1 = sinv[r1];
        float f0[16], f1[16];
        float m0 = -1e30f, m1 = -1e30f;
#pragma unroll
        for (int nt = 0; nt < 8; nt++) {
            f0[2 * nt]     = acc[mt][nt][0] * iv0;
            f0[2 * nt + 1] = acc[mt][nt][1] * iv0;
            f1[2 * nt]     = acc[mt][nt][2] * iv1;
            f1[2 * nt + 1] = acc[mt][nt][3] * iv1;
            m0 = fmaxf(m0, fmaxf(f0[2 * nt], f0[2 * nt + 1]));
            m1 = fmaxf(m1, fmaxf(f1[2 * nt], f1[2 * nt + 1]));
        }
        m0 = fmaxf(m0, __shfl_xor_sync(0xffffffffu, m0, 1));
        m0 = fmaxf(m0, __shfl_xor_sync(0xffffffffu, m0, 2));
        m1 = fmaxf(m1, __shfl_xor_sync(0xffffffffu, m1, 1));
        m1 = fmaxf(m1, __shfl_xor_sync(0xffffffffu, m1, 2));
        float s0 = 0.f, s1 = 0.f;
#pragma unroll
        for (int i = 0; i < 16; i++) {
            f0[i] = __expf(f0[i] - m0); s0 += f0[i];
            f1[i] = __expf(f1[i] - m1); s1 += f1[i];
        }
        s0 += __shfl_xor_sync(0xffffffffu, s0, 1);
        s0 += __shfl_xor_sync(0xffffffffu, s0, 2);
        s1 += __shfl_xor_sync(0xffffffffu, s1, 1);
        s1 += __shfl_xor_sync(0xffffffffu, s1, 2);
        float sc0 = (p0 + r0 < PP) ? shm[r0] / s0 : 0.f;
        float sc1 = (p0 + r1 < PP) ? shm[r1] / s1 : 0.f;
#pragma unroll
        for (int i = 0; i < 16; i++) {
            int col = (i >> 1) * 8 + 2 * q + (i & 1);
            stsf(wst + (u32)(r0 * 65 + col) * 4, f0[i] * sc0);
            stsf(wst + (u32)(r1 * 65 + col) * 4, f1[i] * sc1);
        }
    }
    __syncthreads();

    if (t < 64) {   // raw wsum partial for this p-block
        float sm = 0.f;
        for (int pl = 0; pl < 128; pl++) sm += ldsf(wst + (u32)(pl * 65 + t) * 4);
        g_wsump[(n * NPB + pb) * KK + t] = sm;
    }
    if (pv) {       // w' = w * invn as separate hi/lo bf16 planes
        float iv = sinv[t];
        for (int kk = 0; kk < 64; kk++) {
            float wv = ldsf(wst + (u32)(t * 65 + kk) * 4) * iv;
            __nv_bfloat16 bh = __float2bfloat16_rn(wv);
            float res = wv - __bfloat162float(bh);
            size_t o = ((size_t)n * KK + kk) * PP + p;
            g_whi[o] = __bfloat16_as_ushort(bh);
            g_wlo[o] = __bfloat16_as_ushort(__float2bfloat16_rn(res));
        }
    }
}

__device__ __forceinline__ void k3_fill(u32 bb, int c0, int p0,
                                        const u16* xh, const u16* xl,
                                        const u16* wh, const u16* wl, int t) {
    int ar = t >> 3, acs = (t & 7) * 8;
#pragma unroll
    for (int it = 0; it < 8; it++) {
        int row = ar + it * 16;
        size_t g = (size_t)(c0 + row) * PP + p0 + acs;
        u32 so = (u32)(row * 144 + acs * 2);
        CPA16(bb + K3_AP0 + so, xh + g);
        CPA16(bb + K3_AP1 + so, xl + g);
    }
#pragma unroll
    for (int it = 0; it < 4; it++) {
        int s = t + it * 128;
        int row = s >> 3, cs = (s & 7) * 8;
        size_t g = (size_t)row * PP + p0 + cs;
        u32 so = (u32)(row * 144 + cs * 2);
        CPA16(bb + K3_BP0 + so, wh + g);
        CPA16(bb + K3_BP1 + so, wl + g);
    }
    CPCOMMIT();
}

// ---------------------------------------------------------------------------
// K3: term1 partial MMA D[c,k] = sum_p x[c,p] * w'[k,p]. Double-buffered.
// Grid (4, 48, 2): p-split halves (13/12 stages of 64p).
// ---------------------------------------------------------------------------
__global__ void __launch_bounds__(128) k_vladgemm() {
    extern __shared__ unsigned char dsm[];

    int t = threadIdx.x, wid = t >> 5, lane = t & 31;
    int ct = blockIdx.x, n = blockIdx.y, sp = blockIdx.z;
    int c0 = ct * 128;
    int nst = sp ? 12 : 13;
    int stb = sp * 13;
    const u16* xh = g_xhi + (size_t)n * CC * PP;
    const u16* xl = g_xlo + (size_t)n * CC * PP;
    const u16* wh = g_whi + (size_t)n * KK * PP;
    const u16* wl = g_wlo + (size_t)n * KK * PP;
    u32 base = smem_u32(dsm);

    int gr8 = lane & 7, sel = lane >> 3;
    int lrow = gr8 + (sel & 1) * 8;
    int lcolb = (sel >> 1) * 16;
    u32 aoff = (u32)((wid * 32 + lrow) * 144 + lcolb);
    u32 boff = (u32)(lrow * 144 + lcolb);

    float acc[2][8][4];
#pragma unroll
    for (int mt = 0; mt < 2; mt++)
#pragma unroll
        for (int nt = 0; nt < 8; nt++)
#pragma unroll
            for (int r = 0; r < 4; r++) acc[mt][nt][r] = 0.f;
    __syncthreads();

    k3_fill(base, c0, stb * 64, xh, xl, wh, wl, t);
    for (int st = 0; st < nst; st++) {
        if (st + 1 < nst) {
            k3_fill(base + ((st + 1) & 1) * K3_BUF, c0, (stb + st + 1) * 64, xh, xl, wh, wl, t);
            CPWAIT1();
        } else {
            CPWAIT0();
        }
        __syncthreads();
        u32 bb = base + (st & 1) * K3_BUF;
#pragma unroll
        for (int kc = 0; kc < 4; kc++) {
            u32 ah[2][4], al[2][4];
            u32 aA = bb + K3_AP0 + aoff + (u32)kc * 32;
            ldm4(aA, ah[0]); ldm4(aA + 2304, ah[1]);
            ldm4(aA + (K3_AP1 - K3_AP0), al[0]); ldm4(aA + (K3_AP1 - K3_AP0) + 2304, al[1]);
#pragma unroll
            for (int j = 0; j < 4; j++) {
                u32 bh[4], bl[4];
                u32 aB = bb + K3_BP0 + boff + (u32)j * 2304 + (u32)kc * 32;
                ldm4(aB, bh);
                ldm4(aB + (K3_BP1 - K3_BP0), bl);
#pragma unroll
                for (int mt = 0; mt < 2; mt++) {
                    mma_bf16(acc[mt][2 * j],     ah[mt], bh[0], bh[2]);
                    mma_bf16(acc[mt][2 * j],     ah[mt], bl[0], bl[2]);
                    mma_bf16(acc[mt][2 * j],     al[mt], bh[0], bh[2]);
                    mma_bf16(acc[mt][2 * j + 1], ah[mt], bh[1], bh[3]);
                    mma_bf16(acc[mt][2 * j + 1], ah[mt], bl[1], bl[3]);
                    mma_bf16(acc[mt][2 * j + 1], al[mt], bh[1], bh[3]);
                }
            }
        }
        __syncthreads();
    }

    // stage D[c,k] [128][65] f32 in buffer 0, transpose-write to g_t1 partial
    int gr = lane >> 2, q = lane & 3;
    u32 ds = base;
#pragma unroll
    for (int mt = 0; mt < 2; mt++) {
        int r0 = wid * 32 + mt * 16 + gr;
        int r1 = r0 + 8;
#pragma unroll
        for (int nt = 0; nt < 8; nt++) {
            int col = nt * 8 + 2 * q;
            stsf(ds + (u32)(r0 * 65 + col) * 4,     acc[mt][nt][0]);
            stsf(ds + (u32)(r0 * 65 + col + 1) * 4, acc[mt][nt][1]);
            stsf(ds + (u32)(r1 * 65 + col) * 4,     acc[mt][nt][2]);
            stsf(ds + (u32)(r1 * 65 + col + 1) * 4, acc[mt][nt][3]);
        }
    }
    __syncthreads();
    float* ob = g_t1 + ((size_t)sp * NB + n) * KK * CC;
    for (int kk = 0; kk < 64; kk++)
        ob[(size_t)kk * CC + c0 + t] = ldsf(ds + (u32)(t * 65 + kk) * 4);
}

// ---------------------------------------------------------------------------
// K4: vlad = sum(term1 partials) - wsum*centroid, intra-L2-norm per (n,k).
// ---------------------------------------------------------------------------
__global__ void k_intranorm(float* __restrict__ out,
                            const float* __restrict__ cent) {
    int nk = blockIdx.x;
    int n = nk >> 6, k = nk & 63;
    int t = threadIdx.x;
    float wsv = 0.f;
#pragma unroll
    for (int pb = 0; pb < NPB; pb++) wsv += g_wsump[(n * NPB + pb) * KK + k];
    size_t base = (size_t)nk * CC;
    const float* cb = cent + (size_t)k * CC;
    const size_t TOT = (size_t)NB * KK * CC;

    float v[4];
    float ss = 0.f;
#pragma unroll
    for (int q = 0; q < 4; q++) {
        int c = t + 128 * q;
        float tv = g_t1[base + c] + g_t1[TOT + base + c];
        v[q] = tv - wsv * cb[c];
        ss = fmaf(v[q], v[q], ss);
    }
#pragma unroll
    for (int o = 16; o > 0; o >>= 1) ss += __shfl_xor_sync(0xffffffffu, ss, o);
    __shared__ float sred[4];
    if ((t & 31) == 0) sred[t >> 5] = ss;
    __syncthreads();
    float tot = sred[0] + sred[1] + sred[2] + sred[3];
    float invv = 1.f / fmaxf(sqrtf(tot), EPSV);
#pragma unroll
    for (int q = 0; q < 4; q++) out[base + t + 128 * q] = v[q] * invv;
    if (t == 0) g_knss[nk] = tot * invv * invv;
}

// ---------------------------------------------------------------------------
// K5: global L2 norm per n. Grid (48, 16), 2048 elems per block.
// ---------------------------------------------------------------------------
__global__ void k_globalnorm(float* __restrict__ out) {
    int n = blockIdx.x, t = threadIdx.x;
    float gs = 0.f;
#pragma unroll
    for (int i = 0; i < KK; i++) gs += g_knss[n * KK + i];
    float sc = 1.f / fmaxf(sqrtf(gs), EPSV);
    size_t base = (size_t)n * KK * CC + (size_t)blockIdx.y * 2048;
#pragma unroll
    for (int q = 0; q < 8; q++) out[base + t + 256 * q] *= sc;
}

// ---------------------------------------------------------------------------
extern "C" void kernel_launch(void* const* d_in, const int* in_sizes, int n_in,
                              void* d_out, int out_size) {
    const float* x  = (const float*)d_in[0];   // [48,512,40,40]
    const float* cw = (const float*)d_in[1];   // [64,512]
    const float* aw = (const float*)d_in[2];   // [1,512]
    const float* ab = (const float*)d_in[3];   // [1]
    const float* ct = (const float*)d_in[4];   // [64,512]
    float* out = (float*)d_out;                // [48, 32768]

    cudaFuncSetAttribute(k_assign,   cudaFuncAttributeMaxDynamicSharedMemorySize, SMEM_K2);
    cudaFuncSetAttribute(k_vladgemm, cudaFuncAttributeMaxDynamicSharedMemorySize, SMEM_K3);

    k_pixstats<<<300, 256>>>(x, aw, ab);
    k_cwconv<<<32, 256>>>(cw);
    k_assign<<<dim3(13, 48), 128, SMEM_K2>>>();
    k_vladgemm<<<dim3(4, 48, 2), 128, SMEM_K3>>>();
    k_intranorm<<<NB * KK, 128>>>(out, ct);
    k_globalnorm<<<dim3(48, 16), 256>>>(out);
}